// round 7
// baseline (speedup 1.0000x reference)
#include <cuda_runtime.h>
#include <cstdint>

#define BB  4
#define SS  2048
#define DD  1024
#define HH  16
#define DKK 64
#define NN  (BB*SS)

// ---- warp-MMA GEMM tiling: 512 threads, warp tile 32x32 ----
#define BM   128
#define BN   128
#define BK   16
#define NIT  (DD/BK)            // 64
#define RS   20                 // smem row stride (floats), conflict-free
#define PLANE (BM*RS)           // 2560 floats per plane
#define STAGEF (4*PLANE)        // Ahi,Alo,Bhi,Blo
#define GEMM_SMEM (2*STAGEF*4)  // 81920 bytes

// ---- attention tiling ----
#define TQ   128
#define TKV  64
#define KST  68
#define ATTN_SMEM ((4*64*KST + TQ*KST)*4)   // 104448 bytes

// scratch
__device__ float g_wt[3][DD*DD];
__device__ float g_q[NN*DD];    // [B,S,H,DK] == [8192][1024]
__device__ float g_k[NN*DD];
__device__ float g_v[NN*DD];
__device__ float g_c[NN*DD];

__device__ __forceinline__ float tf32r(float x) {
    uint32_t u;
    asm("cvt.rna.tf32.f32 %0, %1;" : "=r"(u) : "f"(x));
    return __uint_as_float(u);
}
__device__ __forceinline__ void mma8(float* d, const float* a, const float* b) {
    asm volatile("mma.sync.aligned.m16n8k8.row.col.f32.tf32.tf32.f32 "
        "{%0,%1,%2,%3}, {%4,%5,%6,%7}, {%8,%9}, {%0,%1,%2,%3};"
        : "+f"(d[0]), "+f"(d[1]), "+f"(d[2]), "+f"(d[3])
        : "r"(__float_as_uint(a[0])), "r"(__float_as_uint(a[1])),
          "r"(__float_as_uint(a[2])), "r"(__float_as_uint(a[3])),
          "r"(__float_as_uint(b[0])), "r"(__float_as_uint(b[1])));
}

// ---------------------------------------------------------------------------
// Weight transpose: Wt[h*64+dk][d] = W[h][d][dk]
// ---------------------------------------------------------------------------
__global__ void transpose_w(const float* __restrict__ W, float* __restrict__ Wt) {
    __shared__ float t[32][33];
    const int h  = blockIdx.z;
    const int d0 = blockIdx.y << 5;
    const int k0 = blockIdx.x << 5;
    const int c  = threadIdx.x & 31;
    const int r4 = threadIdx.x >> 5;
    const float* Wh = W + ((size_t)h << 16);
    #pragma unroll
    for (int i = 0; i < 4; i++)
        t[r4 + 8*i][c] = Wh[(size_t)(d0 + r4 + 8*i) * DKK + k0 + c];
    __syncthreads();
    float* o = Wt + (size_t)(h * DKK + k0) * DD + d0;
    #pragma unroll
    for (int i = 0; i < 4; i++)
        o[(size_t)(r4 + 8*i) * DD + c] = t[c][r4 + 8*i];
}

// ---------------------------------------------------------------------------
// tf32x3 warp-MMA GEMM: C = A B^T (+bias)
// 512 threads / 16 warps, warp tile 32x32, BK=16 double-buffered,
// split-in-loader (round-3 data path), 4 warps/SMSP for latency hiding.
// ---------------------------------------------------------------------------
__global__ __launch_bounds__(512, 1)
void gemm_tf32(const float* __restrict__ A, const float* __restrict__ B,
               const float* __restrict__ bias, float* __restrict__ C)
{
    extern __shared__ float sm[];
    const int tid  = threadIdx.x;
    const int m0   = blockIdx.y * BM;
    const int n0   = blockIdx.x * BN;
    const int w    = tid >> 5, lane = tid & 31;
    const int grp  = lane >> 2, tig = lane & 3;
    const int m_off = (w & 3) * 32;       // warp m offset (0..96)
    const int n_off = (w >> 2) * 32;      // warp n offset (0..96)

    // loader: 1 float4 per matrix per thread (512 threads = 128 rows x 4 f4)
    const int lrow = tid >> 2, lc4 = (tid & 3) * 4;

    float acc[2][4][4];
    #pragma unroll
    for (int t = 0; t < 2; t++)
        #pragma unroll
        for (int u = 0; u < 4; u++)
            #pragma unroll
            for (int q = 0; q < 4; q++) acc[t][u][q] = 0.f;

    float4 ra, rb;
    ra = *reinterpret_cast<const float4*>(A + (size_t)(m0 + lrow) * DD + lc4);
    rb = *reinterpret_cast<const float4*>(B + (size_t)(n0 + lrow) * DD + lc4);

    #define SPLIT_STORE(stage)                                                    \
    {                                                                             \
        float* AHI = sm + (stage) * STAGEF;                                       \
        float* ALO = AHI + PLANE;                                                 \
        float* BHI = AHI + 2 * PLANE;                                             \
        float* BLO = AHI + 3 * PLANE;                                             \
        float4 h, l;                                                              \
        h.x=tf32r(ra.x); l.x=tf32r(ra.x-h.x); h.y=tf32r(ra.y); l.y=tf32r(ra.y-h.y); \
        h.z=tf32r(ra.z); l.z=tf32r(ra.z-h.z); h.w=tf32r(ra.w); l.w=tf32r(ra.w-h.w); \
        *reinterpret_cast<float4*>(AHI + lrow*RS + lc4) = h;                      \
        *reinterpret_cast<float4*>(ALO + lrow*RS + lc4) = l;                      \
        h.x=tf32r(rb.x); l.x=tf32r(rb.x-h.x); h.y=tf32r(rb.y); l.y=tf32r(rb.y-h.y); \
        h.z=tf32r(rb.z); l.z=tf32r(rb.z-h.z); h.w=tf32r(rb.w); l.w=tf32r(rb.w-h.w); \
        *reinterpret_cast<float4*>(BHI + lrow*RS + lc4) = h;                      \
        *reinterpret_cast<float4*>(BLO + lrow*RS + lc4) = l;                      \
    }

    SPLIT_STORE(0);
    __syncthreads();

    for (int c = 0; c < NIT; ++c) {
        if (c + 1 < NIT) {
            const int k0 = (c + 1) * BK;
            ra = *reinterpret_cast<const float4*>(A + (size_t)(m0 + lrow) * DD + k0 + lc4);
            rb = *reinterpret_cast<const float4*>(B + (size_t)(n0 + lrow) * DD + k0 + lc4);
        }

        const float* AHI = sm + (c & 1) * STAGEF;
        const float* ALO = AHI + PLANE;
        const float* BHI = AHI + 2 * PLANE;
        const float* BLO = AHI + 3 * PLANE;

        #pragma unroll
        for (int s = 0; s < 2; ++s) {
            const int kk = s * 8;
            const int cidx = kk + tig;
            float ah[2][4], al[2][4];
            #pragma unroll
            for (int t = 0; t < 2; t++) {
                const int r = m_off + t * 16 + grp;
                ah[t][0] = AHI[r*RS + cidx];       al[t][0] = ALO[r*RS + cidx];
                ah[t][1] = AHI[(r+8)*RS + cidx];   al[t][1] = ALO[(r+8)*RS + cidx];
                ah[t][2] = AHI[r*RS + cidx + 4];   al[t][2] = ALO[r*RS + cidx + 4];
                ah[t][3] = AHI[(r+8)*RS + cidx+4]; al[t][3] = ALO[(r+8)*RS + cidx+4];
            }
            #pragma unroll
            for (int u = 0; u < 4; u++) {
                const int n = n_off + u * 8 + grp;
                float bh[2], bl[2];
                bh[0] = BHI[n*RS + cidx];     bl[0] = BLO[n*RS + cidx];
                bh[1] = BHI[n*RS + cidx + 4]; bl[1] = BLO[n*RS + cidx + 4];
                #pragma unroll
                for (int t = 0; t < 2; t++) {
                    mma8(acc[t][u], ah[t], bh);
                    mma8(acc[t][u], ah[t], bl);
                    mma8(acc[t][u], al[t], bh);
                }
            }
        }

        if (c + 1 < NIT) SPLIT_STORE((c + 1) & 1);
        __syncthreads();
    }

    const bool hasb = (bias != nullptr);
    #pragma unroll
    for (int u = 0; u < 4; u++) {
        const int ncol = n0 + n_off + u * 8 + tig * 2;
        float2 bv = make_float2(0.f, 0.f);
        if (hasb) bv = *reinterpret_cast<const float2*>(bias + ncol);
        #pragma unroll
        for (int t = 0; t < 2; t++) {
            const int r = m0 + m_off + t * 16 + grp;
            *reinterpret_cast<float2*>(C + (size_t)r * DD + ncol) =
                make_float2(acc[t][u][0] + bv.x, acc[t][u][1] + bv.y);
            *reinterpret_cast<float2*>(C + (size_t)(r + 8) * DD + ncol) =
                make_float2(acc[t][u][2] + bv.x, acc[t][u][3] + bv.y);
        }
    }
    #undef SPLIT_STORE
}

// ---------------------------------------------------------------------------
// Causal flash attention with mma.sync tf32 (round-6 version, unchanged).
// ---------------------------------------------------------------------------
__global__ __launch_bounds__(256, 1)
void attn_mma(const float* __restrict__ gq, const float* __restrict__ gk,
              const float* __restrict__ gv, float* __restrict__ gc)
{
    extern __shared__ float smf[];
    float* Khi  = smf;
    float* Klo  = smf + 64*KST;
    float* Vthi = smf + 2*64*KST;
    float* Vtlo = smf + 3*64*KST;
    float* Ps   = smf + 4*64*KST;

    const int tid  = threadIdx.x;
    const int w    = tid >> 5, lane = tid & 31;
    const int grp  = lane >> 2, tig = lane & 3;
    const int wrow = w * 16;
    const int h    = blockIdx.y, b = blockIdx.z;
    const int st   = gridDim.x - 1 - blockIdx.x;
    const int s0   = st * TQ;

    const float* qb = gq + ((size_t)b * SS + s0) * DD + h * DKK;
    const float* kb = gk + (size_t)b * SS * DD + h * DKK;
    const float* vb = gv + (size_t)b * SS * DD + h * DKK;

    {
        float* Qhi = Ps;
        float* Qlo = Khi;
        #pragma unroll
        for (int u = 0; u < 8; u++) {
            int f = tid + u * 256;
            int row = f >> 4, c4 = f & 15;
            float4 x = *reinterpret_cast<const float4*>(qb + (size_t)row * DD + c4 * 4);
            float4 hv, lv;
            hv.x = tf32r(x.x); lv.x = tf32r(x.x - hv.x);
            hv.y = tf32r(x.y); lv.y = tf32r(x.y - hv.y);
            hv.z = tf32r(x.z); lv.z = tf32r(x.z - hv.z);
            hv.w = tf32r(x.w); lv.w = tf32r(x.w - hv.w);
            *reinterpret_cast<float4*>(Qhi + row * KST + c4 * 4) = hv;
            *reinterpret_cast<float4*>(Qlo + row * KST + c4 * 4) = lv;
        }
    }
    __syncthreads();
    float aqh[8][4], aql[8][4];
    #pragma unroll
    for (int ks = 0; ks < 8; ks++) {
        const int base = (wrow + grp) * KST + ks * 8 + tig;
        aqh[ks][0] = Ps[base];             aqh[ks][1] = Ps[base + 8*KST];
        aqh[ks][2] = Ps[base + 4];         aqh[ks][3] = Ps[base + 8*KST + 4];
        aql[ks][0] = Khi[base];            aql[ks][1] = Khi[base + 8*KST];
        aql[ks][2] = Khi[base + 4];        aql[ks][3] = Khi[base + 8*KST + 4];
    }
    __syncthreads();

    float4 kreg[4], vreg[4];
    #pragma unroll
    for (int u = 0; u < 4; u++) {
        int f = tid + u * 256;
        int row = f >> 4, c4 = f & 15;
        kreg[u] = *reinterpret_cast<const float4*>(kb + (size_t)row * DD + c4 * 4);
        vreg[u] = *reinterpret_cast<const float4*>(vb + (size_t)row * DD + c4 * 4);
    }

    float m0r = -1e30f, m1r = -1e30f, l0 = 0.f, l1 = 0.f;
    float of[8][4];
    #pragma unroll
    for (int nt = 0; nt < 8; nt++)
        #pragma unroll
        for (int q = 0; q < 4; q++) of[nt][q] = 0.f;

    const int ntiles = s0 / TKV + 2;
    for (int tt = 0; tt < ntiles; ++tt) {
        #pragma unroll
        for (int u = 0; u < 4; u++) {
            int f = tid + u * 256;
            int row = f >> 4, c4 = f & 15;
            float4 x = kreg[u];
            float4 hv, lv;
            hv.x = tf32r(x.x); lv.x = tf32r(x.x - hv.x);
            hv.y = tf32r(x.y); lv.y = tf32r(x.y - hv.y);
            hv.z = tf32r(x.z); lv.z = tf32r(x.z - hv.z);
            hv.w = tf32r(x.w); lv.w = tf32r(x.w - hv.w);
            *reinterpret_cast<float4*>(Khi + row * KST + c4 * 4) = hv;
            *reinterpret_cast<float4*>(Klo + row * KST + c4 * 4) = lv;
            float4 y = vreg[u];
            float vh, vl;
            vh = tf32r(y.x); vl = tf32r(y.x - vh);
            Vthi[(c4*4+0)*KST + row] = vh; Vtlo[(c4*4+0)*KST + row] = vl;
            vh = tf32r(y.y); vl = tf32r(y.y - vh);
            Vthi[(c4*4+1)*KST + row] = vh; Vtlo[(c4*4+1)*KST + row] = vl;
            vh = tf32r(y.z); vl = tf32r(y.z - vh);
            Vthi[(c4*4+2)*KST + row] = vh; Vtlo[(c4*4+2)*KST + row] = vl;
            vh = tf32r(y.w); vl = tf32r(y.w - vh);
            Vthi[(c4*4+3)*KST + row] = vh; Vtlo[(c4*4+3)*KST + row] = vl;
        }
        __syncthreads();

        if (tt + 1 < ntiles) {
            const int t0n = (tt + 1) * TKV;
            #pragma unroll
            for (int u = 0; u < 4; u++) {
                int f = tid + u * 256;
                int row = f >> 4, c4 = f & 15;
                kreg[u] = *reinterpret_cast<const float4*>(kb + (size_t)(t0n + row) * DD + c4 * 4);
                vreg[u] = *reinterpret_cast<const float4*>(vb + (size_t)(t0n + row) * DD + c4 * 4);
            }
        }

        float sf[8][4];
        #pragma unroll
        for (int nt = 0; nt < 8; nt++)
            #pragma unroll
            for (int q = 0; q < 4; q++) sf[nt][q] = 0.f;

        #pragma unroll
        for (int ks = 0; ks < 8; ks++) {
            #pragma unroll
            for (int nt = 0; nt < 8; nt++) {
                const int bbx = (nt*8 + grp) * KST + ks*8 + tig;
                float bh[2] = { Khi[bbx], Khi[bbx + 4] };
                float bl[2] = { Klo[bbx], Klo[bbx + 4] };
                mma8(sf[nt], aqh[ks], bh);
                mma8(sf[nt], aql[ks], bh);
                mma8(sf[nt], aqh[ks], bl);
            }
        }

        const int t0 = tt * TKV;
        #pragma unroll
        for (int nt = 0; nt < 8; nt++)
            #pragma unroll
            for (int q = 0; q < 4; q++) sf[nt][q] *= 8.0f;
        if (t0 + TKV > s0) {
            const int r0g = s0 + wrow + grp, r1g = r0g + 8;
            #pragma unroll
            for (int nt = 0; nt < 8; nt++) {
                const int c0g = t0 + nt*8 + 2*tig;
                if (c0g     > r0g) sf[nt][0] = -1e30f;
                if (c0g + 1 > r0g) sf[nt][1] = -1e30f;
                if (c0g     > r1g) sf[nt][2] = -1e30f;
                if (c0g + 1 > r1g) sf[nt][3] = -1e30f;
            }
        }

        float mt0 = -1e30f, mt1 = -1e30f;
        #pragma unroll
        for (int nt = 0; nt < 8; nt++) {
            mt0 = fmaxf(mt0, fmaxf(sf[nt][0], sf[nt][1]));
            mt1 = fmaxf(mt1, fmaxf(sf[nt][2], sf[nt][3]));
        }
        mt0 = fmaxf(mt0, __shfl_xor_sync(0xffffffffu, mt0, 1));
        mt0 = fmaxf(mt0, __shfl_xor_sync(0xffffffffu, mt0, 2));
        mt1 = fmaxf(mt1, __shfl_xor_sync(0xffffffffu, mt1, 1));
        mt1 = fmaxf(mt1, __shfl_xor_sync(0xffffffffu, mt1, 2));

        const float mn0 = fmaxf(m0r, mt0), mn1 = fmaxf(m1r, mt1);
        const float a0 = __expf(m0r - mn0), a1 = __expf(m1r - mn1);
        m0r = mn0; m1r = mn1;

        float s0sum = 0.f, s1sum = 0.f;
        #pragma unroll
        for (int nt = 0; nt < 8; nt++) {
            float p0 = __expf(sf[nt][0] - mn0);
            float p1 = __expf(sf[nt][1] - mn0);
            float p2 = __expf(sf[nt][2] - mn1);
            float p3 = __expf(sf[nt][3] - mn1);
            s0sum += p0 + p1; s1sum += p2 + p3;
            *reinterpret_cast<float2*>(Ps + (wrow + grp) * KST + nt*8 + 2*tig) =
                make_float2(tf32r(p0), tf32r(p1));
            *reinterpret_cast<float2*>(Ps + (wrow + grp + 8) * KST + nt*8 + 2*tig) =
                make_float2(tf32r(p2), tf32r(p3));
        }
        s0sum += __shfl_xor_sync(0xffffffffu, s0sum, 1);
        s0sum += __shfl_xor_sync(0xffffffffu, s0sum, 2);
        s1sum += __shfl_xor_sync(0xffffffffu, s1sum, 1);
        s1sum += __shfl_xor_sync(0xffffffffu, s1sum, 2);
        l0 = l0 * a0 + s0sum;
        l1 = l1 * a1 + s1sum;
        #pragma unroll
        for (int nt = 0; nt < 8; nt++) {
            of[nt][0] *= a0; of[nt][1] *= a0;
            of[nt][2] *= a1; of[nt][3] *= a1;
        }

        #pragma unroll
        for (int ks = 0; ks < 8; ks++) {
            const int ab = (wrow + grp) * KST + ks*8 + tig;
            float ap[4] = { Ps[ab], Ps[ab + 8*KST], Ps[ab + 4], Ps[ab + 8*KST + 4] };
            #pragma unroll
            for (int nt = 0; nt < 8; nt++) {
                const int bbx = (nt*8 + grp) * KST + ks*8 + tig;
                float bh[2] = { Vthi[bbx], Vthi[bbx + 4] };
                float bl[2] = { Vtlo[bbx], Vtlo[bbx + 4] };
                mma8(of[nt], ap, bh);
                mma8(of[nt], ap, bl);
            }
        }
        __syncthreads();
    }

    const float inv0 = 1.0f / l0, inv1 = 1.0f / l1;
    float* ob = gc + ((size_t)b * SS + s0 + wrow + grp) * DD + h * DKK;
    #pragma unroll
    for (int nt = 0; nt < 8; nt++) {
        const int col = nt*8 + 2*tig;
        *reinterpret_cast<float2*>(ob + col) =
            make_float2(of[nt][0] * inv0, of[nt][1] * inv0);
        *reinterpret_cast<float2*>(ob + (size_t)8 * DD + col) =
            make_float2(of[nt][2] * inv1, of[nt][3] * inv1);
    }
}

// ---------------------------------------------------------------------------
extern "C" void kernel_launch(void* const* d_in, const int* in_sizes, int n_in,
                              void* d_out, int out_size)
{
    const float* Q  = (const float*)d_in[0];
    const float* K  = (const float*)d_in[1];
    const float* V  = (const float*)d_in[2];
    // d_in[3] = causal mask (unused)
    const float* Wq = (const float*)d_in[4];
    const float* Wk = (const float*)d_in[5];
    const float* Wv = (const float*)d_in[6];
    const float* Wo = (const float*)d_in[7];
    const float* bo = (const float*)d_in[8];
    float* out = (float*)d_out;

    float *gwt, *gq, *gk, *gv, *gc;
    cudaGetSymbolAddress((void**)&gwt, g_wt);
    cudaGetSymbolAddress((void**)&gq,  g_q);
    cudaGetSymbolAddress((void**)&gk,  g_k);
    cudaGetSymbolAddress((void**)&gv,  g_v);
    cudaGetSymbolAddress((void**)&gc,  g_c);
    float* gwt0 = gwt;
    float* gwt1 = gwt + (size_t)DD * DD;
    float* gwt2 = gwt + 2 * (size_t)DD * DD;

    cudaFuncSetAttribute(gemm_tf32, cudaFuncAttributeMaxDynamicSharedMemorySize, GEMM_SMEM);
    cudaFuncSetAttribute(attn_mma, cudaFuncAttributeMaxDynamicSharedMemorySize, ATTN_SMEM);

    const dim3 tg(DKK / 32, DD / 32, HH);     // (2, 32, 16)
    const dim3 gg(DD / BN, NN / BM);          // (8, 64)

    transpose_w<<<tg, 256>>>(Wq, gwt0);
    transpose_w<<<tg, 256>>>(Wk, gwt1);
    transpose_w<<<tg, 256>>>(Wv, gwt2);
    gemm_tf32<<<gg, 512, GEMM_SMEM>>>(Q, gwt0, nullptr, gq);
    gemm_tf32<<<gg, 512, GEMM_SMEM>>>(K, gwt1, nullptr, gk);
    gemm_tf32<<<gg, 512, GEMM_SMEM>>>(V, gwt2, nullptr, gv);

    attn_mma<<<dim3(SS/TQ, HH, BB), 256, ATTN_SMEM>>>(gq, gk, gv, gc);

    gemm_tf32<<<gg, 512, GEMM_SMEM>>>(gc, Wo, bo, out);
}

// round 8
// speedup vs baseline: 1.9561x; 1.9561x over previous
#include <cuda_runtime.h>
#include <cuda_fp16.h>
#include <cstdint>

#define BB  4
#define SS  2048
#define DD  1024
#define HH  16
#define DKK 64
#define NN  (BB*SS)

// ---- fp16x3 warp-MMA GEMM tiling (round-3 structure, half2-packed) ----
#define BM   128
#define BN   128
#define BK   32                 // 32 fp32 k-elems = 16 half2 "floats" per chunk
#define NIT  (DD/BK)            // 32
#define RS   20                 // smem row stride in half2-float units (proven)
#define PLANE (BM*RS)           // 2560 "floats" per plane
#define STAGEF (4*PLANE)        // Ahi,Alo,Bhi,Blo
#define GEMM_SMEM (2*STAGEF*4)  // 81920 bytes

// ---- attention tiling (half2-packed, stride 36) ----
#define TQ   128
#define TKV  64
#define K36  36                 // row stride in half2-float units
#define PSOFF 9216              // Ps offset (floats): 4 planes x 64*36
#define ATTN_SMEM ((4*64*K36 + 128*K36)*4)   // 55296 bytes

// scratch
__device__ float g_wt[3][DD*DD];
__device__ float g_q[NN*DD];    // [B,S,H,DK] == [8192][1024]
__device__ float g_k[NN*DD];
__device__ float g_v[NN*DD];
__device__ float g_c[NN*DD];

__device__ __forceinline__ uint32_t uf(float x) { return __float_as_uint(x); }

// split 8 consecutive fp32 (two float4) into half2-packed hi/lo uint4s
__device__ __forceinline__ void split8(float4 p, float4 q, uint4& hi, uint4& lo) {
    __half2 h0 = __floats2half2_rn(p.x, p.y);
    __half2 h1 = __floats2half2_rn(p.z, p.w);
    __half2 h2v = __floats2half2_rn(q.x, q.y);
    __half2 h3 = __floats2half2_rn(q.z, q.w);
    float2 f0 = __half22float2(h0), f1 = __half22float2(h1);
    float2 f2 = __half22float2(h2v), f3 = __half22float2(h3);
    __half2 l0 = __floats2half2_rn(p.x - f0.x, p.y - f0.y);
    __half2 l1 = __floats2half2_rn(p.z - f1.x, p.w - f1.y);
    __half2 l2 = __floats2half2_rn(q.x - f2.x, q.y - f2.y);
    __half2 l3 = __floats2half2_rn(q.z - f3.x, q.w - f3.y);
    hi = make_uint4(*(uint32_t*)&h0, *(uint32_t*)&h1, *(uint32_t*)&h2v, *(uint32_t*)&h3);
    lo = make_uint4(*(uint32_t*)&l0, *(uint32_t*)&l1, *(uint32_t*)&l2, *(uint32_t*)&l3);
}

__device__ __forceinline__ void mma16(float* d, const uint32_t* a, uint32_t b0, uint32_t b1) {
    asm volatile("mma.sync.aligned.m16n8k16.row.col.f32.f16.f16.f32 "
        "{%0,%1,%2,%3},{%4,%5,%6,%7},{%8,%9},{%0,%1,%2,%3};"
        : "+f"(d[0]), "+f"(d[1]), "+f"(d[2]), "+f"(d[3])
        : "r"(a[0]), "r"(a[1]), "r"(a[2]), "r"(a[3]), "r"(b0), "r"(b1));
}

// ---------------------------------------------------------------------------
// Weight transpose: Wt[h*64+dk][d] = W[h][d][dk]
// ---------------------------------------------------------------------------
__global__ void transpose_w(const float* __restrict__ W, float* __restrict__ Wt) {
    __shared__ float t[32][33];
    const int h  = blockIdx.z;
    const int d0 = blockIdx.y << 5;
    const int k0 = blockIdx.x << 5;
    const int c  = threadIdx.x & 31;
    const int r4 = threadIdx.x >> 5;
    const float* Wh = W + ((size_t)h << 16);
    #pragma unroll
    for (int i = 0; i < 4; i++)
        t[r4 + 8*i][c] = Wh[(size_t)(d0 + r4 + 8*i) * DKK + k0 + c];
    __syncthreads();
    float* o = Wt + (size_t)(h * DKK + k0) * DD + d0;
    #pragma unroll
    for (int i = 0; i < 4; i++)
        o[(size_t)(r4 + 8*i) * DD + c] = t[c][r4 + 8*i];
}

// ---------------------------------------------------------------------------
// fp16x3 warp-MMA GEMM: C = A B^T (+bias).  Split-in-loader, BK=32,
// double-buffered smem (half2 planes viewed as float), warp tile 64x32.
// ---------------------------------------------------------------------------
__global__ __launch_bounds__(256, 1)
void gemm_fp16(const float* __restrict__ A, const float* __restrict__ B,
               const float* __restrict__ bias, float* __restrict__ C)
{
    extern __shared__ float sm[];
    const int tid  = threadIdx.x;
    const int m0   = blockIdx.y * BM;
    const int n0   = blockIdx.x * BN;
    const int w    = tid >> 5, lane = tid & 31;
    const int grp  = lane >> 2, tig = lane & 3;
    const int m_off = (w >> 2) * 64;
    const int n_off = (w & 3) * 32;

    // loader: 2 tasks of (row, oct) covering 128 rows x 4 octets (8 floats each)
    const int r0l = tid >> 2,            o0l = tid & 3;
    const int r1l = (tid + 256) >> 2,    o1l = o0l;   // f=tid+256: oct same low bits

    float acc[4][4][4];
    #pragma unroll
    for (int t = 0; t < 4; t++)
        #pragma unroll
        for (int u = 0; u < 4; u++)
            #pragma unroll
            for (int q = 0; q < 4; q++) acc[t][u][q] = 0.f;

    float4 ra[2][2], rb[2][2];
    #pragma unroll
    for (int u = 0; u < 2; u++) {
        const int rr = u ? r1l : r0l, oo = u ? o1l : o0l;
        ra[u][0] = *reinterpret_cast<const float4*>(A + (size_t)(m0 + rr) * DD + oo * 8);
        ra[u][1] = *reinterpret_cast<const float4*>(A + (size_t)(m0 + rr) * DD + oo * 8 + 4);
        rb[u][0] = *reinterpret_cast<const float4*>(B + (size_t)(n0 + rr) * DD + oo * 8);
        rb[u][1] = *reinterpret_cast<const float4*>(B + (size_t)(n0 + rr) * DD + oo * 8 + 4);
    }

    #define SPLIT_STORE(stage)                                                    \
    {                                                                             \
        float* AHI = sm + (stage) * STAGEF;                                       \
        float* ALO = AHI + PLANE;                                                 \
        float* BHI = AHI + 2 * PLANE;                                             \
        float* BLO = AHI + 3 * PLANE;                                             \
        uint4 hi, lo;                                                             \
        _Pragma("unroll")                                                         \
        for (int u = 0; u < 2; u++) {                                             \
            const int rr = u ? r1l : r0l, oo = u ? o1l : o0l;                     \
            split8(ra[u][0], ra[u][1], hi, lo);                                   \
            *reinterpret_cast<uint4*>(AHI + rr*RS + oo*4) = hi;                   \
            *reinterpret_cast<uint4*>(ALO + rr*RS + oo*4) = lo;                   \
            split8(rb[u][0], rb[u][1], hi, lo);                                   \
            *reinterpret_cast<uint4*>(BHI + rr*RS + oo*4) = hi;                   \
            *reinterpret_cast<uint4*>(BLO + rr*RS + oo*4) = lo;                   \
        }                                                                         \
    }

    SPLIT_STORE(0);
    __syncthreads();

    for (int c = 0; c < NIT; ++c) {
        if (c + 1 < NIT) {
            const int k0 = (c + 1) * BK;
            #pragma unroll
            for (int u = 0; u < 2; u++) {
                const int rr = u ? r1l : r0l, oo = u ? o1l : o0l;
                ra[u][0] = *reinterpret_cast<const float4*>(A + (size_t)(m0 + rr) * DD + k0 + oo * 8);
                ra[u][1] = *reinterpret_cast<const float4*>(A + (size_t)(m0 + rr) * DD + k0 + oo * 8 + 4);
                rb[u][0] = *reinterpret_cast<const float4*>(B + (size_t)(n0 + rr) * DD + k0 + oo * 8);
                rb[u][1] = *reinterpret_cast<const float4*>(B + (size_t)(n0 + rr) * DD + k0 + oo * 8 + 4);
            }
        }

        const float* AHI = sm + (c & 1) * STAGEF;
        const float* ALO = AHI + PLANE;
        const float* BHI = AHI + 2 * PLANE;
        const float* BLO = AHI + 3 * PLANE;

        #pragma unroll
        for (int s = 0; s < 2; ++s) {
            const int cidx = s * 8 + tig;
            uint32_t ah[4][4], al[4][4];
            #pragma unroll
            for (int t = 0; t < 4; t++) {
                const int r = m_off + t * 16 + grp;
                ah[t][0] = uf(AHI[r*RS + cidx]);       al[t][0] = uf(ALO[r*RS + cidx]);
                ah[t][1] = uf(AHI[(r+8)*RS + cidx]);   al[t][1] = uf(ALO[(r+8)*RS + cidx]);
                ah[t][2] = uf(AHI[r*RS + cidx + 4]);   al[t][2] = uf(ALO[r*RS + cidx + 4]);
                ah[t][3] = uf(AHI[(r+8)*RS + cidx+4]); al[t][3] = uf(ALO[(r+8)*RS + cidx+4]);
            }
            #pragma unroll
            for (int u = 0; u < 4; u++) {
                const int n = n_off + u * 8 + grp;
                uint32_t bh0 = uf(BHI[n*RS + cidx]),     bl0 = uf(BLO[n*RS + cidx]);
                uint32_t bh1 = uf(BHI[n*RS + cidx + 4]), bl1 = uf(BLO[n*RS + cidx + 4]);
                #pragma unroll
                for (int t = 0; t < 4; t++) {
                    mma16(acc[t][u], ah[t], bh0, bh1);
                    mma16(acc[t][u], ah[t], bl0, bl1);
                    mma16(acc[t][u], al[t], bh0, bh1);
                }
            }
        }

        if (c + 1 < NIT) SPLIT_STORE((c + 1) & 1);
        __syncthreads();
    }

    const bool hasb = (bias != nullptr);
    #pragma unroll
    for (int u = 0; u < 4; u++) {
        const int ncol = n0 + n_off + u * 8 + tig * 2;
        float2 bv = make_float2(0.f, 0.f);
        if (hasb) bv = *reinterpret_cast<const float2*>(bias + ncol);
        #pragma unroll
        for (int t = 0; t < 4; t++) {
            const int r = m0 + m_off + t * 16 + grp;
            *reinterpret_cast<float2*>(C + (size_t)r * DD + ncol) =
                make_float2(acc[t][u][0] + bv.x, acc[t][u][1] + bv.y);
            *reinterpret_cast<float2*>(C + (size_t)(r + 8) * DD + ncol) =
                make_float2(acc[t][u][2] + bv.x, acc[t][u][3] + bv.y);
        }
    }
    #undef SPLIT_STORE
}

// ---------------------------------------------------------------------------
// Causal flash attention, fp16 mma.  QK: x3 (q,k hi/lo). PV: P fp16, V hi/lo x2.
// CTA: 128 q-rows, 8 warps (m16 x 64kv x 64dk each). scale = 8.
// ---------------------------------------------------------------------------
__global__ __launch_bounds__(256, 1)
void attn_mma(const float* __restrict__ gq, const float* __restrict__ gk,
              const float* __restrict__ gv, float* __restrict__ gc)
{
    extern __shared__ float smf[];
    float* Khi  = smf;                 // [64][K36] K natural, half2 along dk
    float* Klo  = smf + 64*K36;
    float* Vthi = smf + 2*64*K36;      // [64 dk][K36] V^T, half2 packs kv pairs
    float* Vtlo = smf + 3*64*K36;
    float* Ps   = smf + PSOFF;         // [128][K36] P half2 / Q-hi staging

    const int tid  = threadIdx.x;
    const int w    = tid >> 5, lane = tid & 31;
    const int grp  = lane >> 2, tig = lane & 3;
    const int wrow = w * 16;
    const int h    = blockIdx.y, b = blockIdx.z;
    const int st   = gridDim.x - 1 - blockIdx.x;
    const int s0   = st * TQ;

    const float* qb = gq + ((size_t)b * SS + s0) * DD + h * DKK;
    const float* kb = gk + (size_t)b * SS * DD + h * DKK;
    const float* vb = gv + (size_t)b * SS * DD + h * DKK;

    // ---- stage Q split (Qhi->Ps, Qlo->Khi area) ----
    {
        float* Qlo = smf;
        #pragma unroll
        for (int u = 0; u < 4; u++) {
            int f = tid + u * 256;
            int row = f >> 3, oct = f & 7;
            float4 x0 = *reinterpret_cast<const float4*>(qb + (size_t)row * DD + oct * 8);
            float4 x1 = *reinterpret_cast<const float4*>(qb + (size_t)row * DD + oct * 8 + 4);
            uint4 hi, lo;
            split8(x0, x1, hi, lo);
            *reinterpret_cast<uint4*>(Ps  + row * K36 + oct * 4) = hi;
            *reinterpret_cast<uint4*>(Qlo + row * K36 + oct * 4) = lo;
        }
    }
    __syncthreads();
    uint32_t aqh[4][4], aql[4][4];
    #pragma unroll
    for (int ks = 0; ks < 4; ks++) {
        const int c0 = ks * 8 + tig;
        const int ra = (wrow + grp) * K36, rb2 = (wrow + grp + 8) * K36;
        aqh[ks][0] = uf(Ps[ra + c0]);      aqh[ks][1] = uf(Ps[rb2 + c0]);
        aqh[ks][2] = uf(Ps[ra + c0 + 4]);  aqh[ks][3] = uf(Ps[rb2 + c0 + 4]);
        aql[ks][0] = uf(smf[ra + c0]);     aql[ks][1] = uf(smf[rb2 + c0]);
        aql[ks][2] = uf(smf[ra + c0 + 4]); aql[ks][3] = uf(smf[rb2 + c0 + 4]);
    }
    __syncthreads();

    // prefetch K/V tile 0
    const int kr0 = tid >> 3,          ko0 = tid & 7;     // K task 0
    const int kr1 = (tid + 256) >> 3;                     // K task 1 (same oct)
    const int vl  = lane, vw8 = w * 8;                    // V: rows 2*vl, cols vw8..+7
    float4 kreg[2][2], vreg[4];
    #pragma unroll
    for (int u = 0; u < 2; u++) {
        const int rr = u ? kr1 : kr0;
        kreg[u][0] = *reinterpret_cast<const float4*>(kb + (size_t)rr * DD + ko0 * 8);
        kreg[u][1] = *reinterpret_cast<const float4*>(kb + (size_t)rr * DD + ko0 * 8 + 4);
    }
    vreg[0] = *reinterpret_cast<const float4*>(vb + (size_t)(2*vl)   * DD + vw8);
    vreg[1] = *reinterpret_cast<const float4*>(vb + (size_t)(2*vl)   * DD + vw8 + 4);
    vreg[2] = *reinterpret_cast<const float4*>(vb + (size_t)(2*vl+1) * DD + vw8);
    vreg[3] = *reinterpret_cast<const float4*>(vb + (size_t)(2*vl+1) * DD + vw8 + 4);

    float m0r = -1e30f, m1r = -1e30f, l0 = 0.f, l1 = 0.f;
    float of[8][4];
    #pragma unroll
    for (int nt = 0; nt < 8; nt++)
        #pragma unroll
        for (int q = 0; q < 4; q++) of[nt][q] = 0.f;

    const int ntiles = s0 / TKV + 2;
    for (int tt = 0; tt < ntiles; ++tt) {
        // store prefetched K (natural half2) and V (transposed kv-pair half2)
        #pragma unroll
        for (int u = 0; u < 2; u++) {
            const int rr = u ? kr1 : kr0;
            uint4 hi, lo;
            split8(kreg[u][0], kreg[u][1], hi, lo);
            *reinterpret_cast<uint4*>(Khi + rr * K36 + ko0 * 4) = hi;
            *reinterpret_cast<uint4*>(Klo + rr * K36 + ko0 * 4) = lo;
        }
        {
            const float* a0 = reinterpret_cast<const float*>(&vreg[0]);   // row 2l cols 0..7
            const float* a1 = reinterpret_cast<const float*>(&vreg[2]);   // row 2l+1
            #pragma unroll
            for (int j = 0; j < 8; j++) {
                float x = a0[j], y = a1[j];
                __half2 hh = __floats2half2_rn(x, y);
                float2 hf = __half22float2(hh);
                __half2 ll = __floats2half2_rn(x - hf.x, y - hf.y);
                Vthi[(vw8 + j) * K36 + vl] = __uint_as_float(*(uint32_t*)&hh);
                Vtlo[(vw8 + j) * K36 + vl] = __uint_as_float(*(uint32_t*)&ll);
            }
        }
        __syncthreads();

        // prefetch next tile
        if (tt + 1 < ntiles) {
            const int t0n = (tt + 1) * TKV;
            #pragma unroll
            for (int u = 0; u < 2; u++) {
                const int rr = (u ? kr1 : kr0) + t0n;
                kreg[u][0] = *reinterpret_cast<const float4*>(kb + (size_t)rr * DD + ko0 * 8);
                kreg[u][1] = *reinterpret_cast<const float4*>(kb + (size_t)rr * DD + ko0 * 8 + 4);
            }
            vreg[0] = *reinterpret_cast<const float4*>(vb + (size_t)(t0n+2*vl)   * DD + vw8);
            vreg[1] = *reinterpret_cast<const float4*>(vb + (size_t)(t0n+2*vl)   * DD + vw8 + 4);
            vreg[2] = *reinterpret_cast<const float4*>(vb + (size_t)(t0n+2*vl+1) * DD + vw8);
            vreg[3] = *reinterpret_cast<const float4*>(vb + (size_t)(t0n+2*vl+1) * DD + vw8 + 4);
        }

        // ---- S = Q K^T (fp16 x3) ----
        float sf[8][4];
        #pragma unroll
        for (int nt = 0; nt < 8; nt++)
            #pragma unroll
            for (int q = 0; q < 4; q++) sf[nt][q] = 0.f;

        #pragma unroll
        for (int ks = 0; ks < 4; ks++) {
            const int c0 = ks * 8 + tig;
            #pragma unroll
            for (int nt = 0; nt < 8; nt++) {
                const int n = (nt * 8 + grp) * K36;
                uint32_t bh0 = uf(Khi[n + c0]),     bl0 = uf(Klo[n + c0]);
                uint32_t bh1 = uf(Khi[n + c0 + 4]), bl1 = uf(Klo[n + c0 + 4]);
                mma16(sf[nt], aqh[ks], bh0, bh1);
                mma16(sf[nt], aql[ks], bh0, bh1);
                mma16(sf[nt], aqh[ks], bl0, bl1);
            }
        }

        const int t0 = tt * TKV;
        #pragma unroll
        for (int nt = 0; nt < 8; nt++)
            #pragma unroll
            for (int q = 0; q < 4; q++) sf[nt][q] *= 8.0f;
        if (t0 + TKV > s0) {
            const int r0g = s0 + wrow + grp, r1g = r0g + 8;
            #pragma unroll
            for (int nt = 0; nt < 8; nt++) {
                const int c0g = t0 + nt*8 + 2*tig;
                if (c0g     > r0g) sf[nt][0] = -1e30f;
                if (c0g + 1 > r0g) sf[nt][1] = -1e30f;
                if (c0g     > r1g) sf[nt][2] = -1e30f;
                if (c0g + 1 > r1g) sf[nt][3] = -1e30f;
            }
        }

        float mt0 = -1e30f, mt1 = -1e30f;
        #pragma unroll
        for (int nt = 0; nt < 8; nt++) {
            mt0 = fmaxf(mt0, fmaxf(sf[nt][0], sf[nt][1]));
            mt1 = fmaxf(mt1, fmaxf(sf[nt][2], sf[nt][3]));
        }
        mt0 = fmaxf(mt0, __shfl_xor_sync(0xffffffffu, mt0, 1));
        mt0 = fmaxf(mt0, __shfl_xor_sync(0xffffffffu, mt0, 2));
        mt1 = fmaxf(mt1, __shfl_xor_sync(0xffffffffu, mt1, 1));
        mt1 = fmaxf(mt1, __shfl_xor_sync(0xffffffffu, mt1, 2));

        const float mn0 = fmaxf(m0r, mt0), mn1 = fmaxf(m1r, mt1);
        const float a0s = __expf(m0r - mn0), a1s = __expf(m1r - mn1);
        m0r = mn0; m1r = mn1;

        float s0sum = 0.f, s1sum = 0.f;
        #pragma unroll
        for (int nt = 0; nt < 8; nt++) {
            float p0 = __expf(sf[nt][0] - mn0);
            float p1 = __expf(sf[nt][1] - mn0);
            float p2 = __expf(sf[nt][2] - mn1);
            float p3 = __expf(sf[nt][3] - mn1);
            s0sum += p0 + p1; s1sum += p2 + p3;
            __half2 hp0 = __floats2half2_rn(p0, p1);
            __half2 hp1 = __floats2half2_rn(p2, p3);
            Ps[(wrow + grp)     * K36 + nt*4 + tig] = __uint_as_float(*(uint32_t*)&hp0);
            Ps[(wrow + grp + 8) * K36 + nt*4 + tig] = __uint_as_float(*(uint32_t*)&hp1);
        }
        s0sum += __shfl_xor_sync(0xffffffffu, s0sum, 1);
        s0sum += __shfl_xor_sync(0xffffffffu, s0sum, 2);
        s1sum += __shfl_xor_sync(0xffffffffu, s1sum, 1);
        s1sum += __shfl_xor_sync(0xffffffffu, s1sum, 2);
        l0 = l0 * a0s + s0sum;
        l1 = l1 * a1s + s1sum;
        #pragma unroll
        for (int nt = 0; nt < 8; nt++) {
            of[nt][0] *= a0s; of[nt][1] *= a0s;
            of[nt][2] *= a1s; of[nt][3] *= a1s;
        }

        // ---- O += P V (P fp16, V hi/lo) ----  (Ps rows warp-private)
        #pragma unroll
        for (int ks = 0; ks < 4; ks++) {
            const int c0 = ks * 8 + tig;
            uint32_t ap[4];
            ap[0] = uf(Ps[(wrow + grp)     * K36 + c0]);
            ap[1] = uf(Ps[(wrow + grp + 8) * K36 + c0]);
            ap[2] = uf(Ps[(wrow + grp)     * K36 + c0 + 4]);
            ap[3] = uf(Ps[(wrow + grp + 8) * K36 + c0 + 4]);
            #pragma unroll
            for (int nt = 0; nt < 8; nt++) {
                const int n = (nt * 8 + grp) * K36;
                uint32_t bh0 = uf(Vthi[n + c0]),     bl0 = uf(Vtlo[n + c0]);
                uint32_t bh1 = uf(Vthi[n + c0 + 4]), bl1 = uf(Vtlo[n + c0 + 4]);
                mma16(of[nt], ap, bh0, bh1);
                mma16(of[nt], ap, bl0, bl1);
            }
        }
        __syncthreads();
    }

    const float inv0 = 1.0f / l0, inv1 = 1.0f / l1;
    float* ob = gc + ((size_t)b * SS + s0 + wrow + grp) * DD + h * DKK;
    #pragma unroll
    for (int nt = 0; nt < 8; nt++) {
        const int col = nt*8 + 2*tig;
        *reinterpret_cast<float2*>(ob + col) =
            make_float2(of[nt][0] * inv0, of[nt][1] * inv0);
        *reinterpret_cast<float2*>(ob + (size_t)8 * DD + col) =
            make_float2(of[nt][2] * inv1, of[nt][3] * inv1);
    }
}

// ---------------------------------------------------------------------------
extern "C" void kernel_launch(void* const* d_in, const int* in_sizes, int n_in,
                              void* d_out, int out_size)
{
    const float* Q  = (const float*)d_in[0];
    const float* K  = (const float*)d_in[1];
    const float* V  = (const float*)d_in[2];
    // d_in[3] = causal mask (unused)
    const float* Wq = (const float*)d_in[4];
    const float* Wk = (const float*)d_in[5];
    const float* Wv = (const float*)d_in[6];
    const float* Wo = (const float*)d_in[7];
    const float* bo = (const float*)d_in[8];
    float* out = (float*)d_out;

    float *gwt, *gq, *gk, *gv, *gc;
    cudaGetSymbolAddress((void**)&gwt, g_wt);
    cudaGetSymbolAddress((void**)&gq,  g_q);
    cudaGetSymbolAddress((void**)&gk,  g_k);
    cudaGetSymbolAddress((void**)&gv,  g_v);
    cudaGetSymbolAddress((void**)&gc,  g_c);
    float* gwt0 = gwt;
    float* gwt1 = gwt + (size_t)DD * DD;
    float* gwt2 = gwt + 2 * (size_t)DD * DD;

    cudaFuncSetAttribute(gemm_fp16, cudaFuncAttributeMaxDynamicSharedMemorySize, GEMM_SMEM);
    cudaFuncSetAttribute(attn_mma, cudaFuncAttributeMaxDynamicSharedMemorySize, ATTN_SMEM);

    const dim3 tg(DKK / 32, DD / 32, HH);     // (2, 32, 16)
    const dim3 gg(DD / BN, NN / BM);          // (8, 64)

    transpose_w<<<tg, 256>>>(Wq, gwt0);
    transpose_w<<<tg, 256>>>(Wk, gwt1);
    transpose_w<<<tg, 256>>>(Wv, gwt2);
    gemm_fp16<<<gg, 256, GEMM_SMEM>>>(Q, gwt0, nullptr, gq);
    gemm_fp16<<<gg, 256, GEMM_SMEM>>>(K, gwt1, nullptr, gk);
    gemm_fp16<<<gg, 256, GEMM_SMEM>>>(V, gwt2, nullptr, gv);

    attn_mma<<<dim3(SS/TQ, HH, BB), 256, ATTN_SMEM>>>(gq, gk, gv, gc);

    gemm_fp16<<<gg, 256, GEMM_SMEM>>>(gc, Wo, bo, out);
}

// round 9
// speedup vs baseline: 2.1851x; 1.1171x over previous
#include <cuda_runtime.h>
#include <cuda_fp16.h>
#include <cstdint>

#define BB  4
#define SS  2048
#define DD  1024
#define HH  16
#define DKK 64
#define NN  (BB*SS)

// ---- fp16x3 warp-MMA GEMM tiling ----
#define BM   128
#define BN   128
#define BK   32                 // 32 fp32 k-elems = 16 half2 words per chunk
#define NIT  (DD/BK)            // 32
#define RS   20                 // smem row stride in half2-word units
#define PLANE (BM*RS)
#define STAGEF (4*PLANE)
#define GEMM_SMEM (2*STAGEF*4)  // 81920 bytes

// ---- attention tiling ----
#define TQ   128
#define TKV  64
#define K36  36
#define PSOFF 9216
#define ATTN_SMEM ((4*64*K36 + 128*K36)*4)   // 55296 bytes

// scratch
__device__ float g_wt[3][DD*DD];   // contiguous [3072][1024] K-major qkv weights
__device__ float g_q[NN*DD];
__device__ float g_k[NN*DD];
__device__ float g_v[NN*DD];
__device__ float g_c[NN*DD];

__device__ __forceinline__ uint32_t uf(float x) { return __float_as_uint(x); }
__device__ __forceinline__ uint32_t smem_u32(const void* p) {
    uint32_t a;
    asm("{ .reg .u64 t; cvta.to.shared.u64 t, %1; cvt.u32.u64 %0, t; }" : "=r"(a) : "l"(p));
    return a;
}
__device__ __forceinline__ void ldm4(uint32_t* r, uint32_t a) {
    asm volatile("ldmatrix.sync.aligned.m8n8.x4.shared.b16 {%0,%1,%2,%3}, [%4];"
        : "=r"(r[0]), "=r"(r[1]), "=r"(r[2]), "=r"(r[3]) : "r"(a));
}

// split 8 consecutive fp32 (two float4) into half2-packed hi/lo uint4s
__device__ __forceinline__ void split8(float4 p, float4 q, uint4& hi, uint4& lo) {
    __half2 h0 = __floats2half2_rn(p.x, p.y);
    __half2 h1 = __floats2half2_rn(p.z, p.w);
    __half2 h2v = __floats2half2_rn(q.x, q.y);
    __half2 h3 = __floats2half2_rn(q.z, q.w);
    float2 f0 = __half22float2(h0), f1 = __half22float2(h1);
    float2 f2 = __half22float2(h2v), f3 = __half22float2(h3);
    __half2 l0 = __floats2half2_rn(p.x - f0.x, p.y - f0.y);
    __half2 l1 = __floats2half2_rn(p.z - f1.x, p.w - f1.y);
    __half2 l2 = __floats2half2_rn(q.x - f2.x, q.y - f2.y);
    __half2 l3 = __floats2half2_rn(q.z - f3.x, q.w - f3.y);
    hi = make_uint4(*(uint32_t*)&h0, *(uint32_t*)&h1, *(uint32_t*)&h2v, *(uint32_t*)&h3);
    lo = make_uint4(*(uint32_t*)&l0, *(uint32_t*)&l1, *(uint32_t*)&l2, *(uint32_t*)&l3);
}

__device__ __forceinline__ void mma16(float* d, const uint32_t* a, uint32_t b0, uint32_t b1) {
    asm volatile("mma.sync.aligned.m16n8k16.row.col.f32.f16.f16.f32 "
        "{%0,%1,%2,%3},{%4,%5,%6,%7},{%8,%9},{%0,%1,%2,%3};"
        : "+f"(d[0]), "+f"(d[1]), "+f"(d[2]), "+f"(d[3])
        : "r"(a[0]), "r"(a[1]), "r"(a[2]), "r"(a[3]), "r"(b0), "r"(b1));
}

// ---------------------------------------------------------------------------
// Weight transpose: Wt[h*64+dk][d] = W[h][d][dk]
// ---------------------------------------------------------------------------
__global__ void transpose_w(const float* __restrict__ W, float* __restrict__ Wt) {
    __shared__ float t[32][33];
    const int h  = blockIdx.z;
    const int d0 = blockIdx.y << 5;
    const int k0 = blockIdx.x << 5;
    const int c  = threadIdx.x & 31;
    const int r4 = threadIdx.x >> 5;
    const float* Wh = W + ((size_t)h << 16);
    #pragma unroll
    for (int i = 0; i < 4; i++)
        t[r4 + 8*i][c] = Wh[(size_t)(d0 + r4 + 8*i) * DKK + k0 + c];
    __syncthreads();
    float* o = Wt + (size_t)(h * DKK + k0) * DD + d0;
    #pragma unroll
    for (int i = 0; i < 4; i++)
        o[(size_t)(r4 + 8*i) * DD + c] = t[c][r4 + 8*i];
}

// ---------------------------------------------------------------------------
// fp16x3 warp-MMA GEMM with ldmatrix fragments and N-segment fusion:
// column segment seg = n0/1024 selects A in {A0,A1,A2} and C in {C0,C1,C2}.
// ---------------------------------------------------------------------------
__global__ __launch_bounds__(256, 1)
void gemm_fp16(const float* __restrict__ A0, const float* __restrict__ A1,
               const float* __restrict__ A2, const float* __restrict__ Bw,
               const float* __restrict__ bias,
               float* __restrict__ C0, float* __restrict__ C1, float* __restrict__ C2)
{
    extern __shared__ float sm[];
    const uint32_t smb = smem_u32(sm);
    const int tid  = threadIdx.x;
    const int m0   = blockIdx.y * BM;
    const int n0g  = blockIdx.x * BN;         // global col in [0, 3N)
    const int seg  = n0g >> 10;
    const int n0   = n0g & (DD - 1);          // col within segment
    const float* A = (seg == 0) ? A0 : (seg == 1) ? A1 : A2;
    float*       C = (seg == 0) ? C0 : (seg == 1) ? C1 : C2;

    const int w    = tid >> 5, lane = tid & 31;
    const int grp  = lane >> 2, tig = lane & 3;
    const int m_off = (w >> 2) * 64;
    const int n_off = (w & 3) * 32;

    // ldmatrix lane->address components (in half2-word units)
    const int a_row = lane & 15;              // + m_off + t*16
    const int a_k   = (lane >> 4) * 4;
    const int b_row = (lane & 7) + ((lane >> 1) & 8);   // + n_off + u2*16
    const int b_k   = ((lane >> 3) & 1) * 4;

    // loader: 2 tasks of (row, oct) covering 128 rows x 4 octets (8 floats each)
    const int r0l = tid >> 2, o0l = tid & 3;
    const int r1l = (tid + 256) >> 2;

    float acc[4][4][4];
    #pragma unroll
    for (int t = 0; t < 4; t++)
        #pragma unroll
        for (int u = 0; u < 4; u++)
            #pragma unroll
            for (int q = 0; q < 4; q++) acc[t][u][q] = 0.f;

    float4 ra[2][2], rb[2][2];
    #pragma unroll
    for (int u = 0; u < 2; u++) {
        const int rr = u ? r1l : r0l;
        ra[u][0] = *reinterpret_cast<const float4*>(A + (size_t)(m0 + rr) * DD + o0l * 8);
        ra[u][1] = *reinterpret_cast<const float4*>(A + (size_t)(m0 + rr) * DD + o0l * 8 + 4);
        rb[u][0] = *reinterpret_cast<const float4*>(Bw + (size_t)(n0g + rr) * DD + o0l * 8);
        rb[u][1] = *reinterpret_cast<const float4*>(Bw + (size_t)(n0g + rr) * DD + o0l * 8 + 4);
    }

    #define SPLIT_STORE(stage)                                                    \
    {                                                                             \
        float* AHI = sm + (stage) * STAGEF;                                       \
        float* ALO = AHI + PLANE;                                                 \
        float* BHI = AHI + 2 * PLANE;                                             \
        float* BLO = AHI + 3 * PLANE;                                             \
        uint4 hi, lo;                                                             \
        _Pragma("unroll")                                                         \
        for (int u = 0; u < 2; u++) {                                             \
            const int rr = u ? r1l : r0l;                                         \
            split8(ra[u][0], ra[u][1], hi, lo);                                   \
            *reinterpret_cast<uint4*>(AHI + rr*RS + o0l*4) = hi;                  \
            *reinterpret_cast<uint4*>(ALO + rr*RS + o0l*4) = lo;                  \
            split8(rb[u][0], rb[u][1], hi, lo);                                   \
            *reinterpret_cast<uint4*>(BHI + rr*RS + o0l*4) = hi;                  \
            *reinterpret_cast<uint4*>(BLO + rr*RS + o0l*4) = lo;                  \
        }                                                                         \
    }

    SPLIT_STORE(0);
    __syncthreads();

    for (int c = 0; c < NIT; ++c) {
        if (c + 1 < NIT) {
            const int k0 = (c + 1) * BK;
            #pragma unroll
            for (int u = 0; u < 2; u++) {
                const int rr = u ? r1l : r0l;
                ra[u][0] = *reinterpret_cast<const float4*>(A + (size_t)(m0 + rr) * DD + k0 + o0l * 8);
                ra[u][1] = *reinterpret_cast<const float4*>(A + (size_t)(m0 + rr) * DD + k0 + o0l * 8 + 4);
                rb[u][0] = *reinterpret_cast<const float4*>(Bw + (size_t)(n0g + rr) * DD + k0 + o0l * 8);
                rb[u][1] = *reinterpret_cast<const float4*>(Bw + (size_t)(n0g + rr) * DD + k0 + o0l * 8 + 4);
            }
        }

        const uint32_t sbase = smb + (uint32_t)(c & 1) * (STAGEF * 4u);

        #pragma unroll
        for (int s = 0; s < 2; ++s) {
            uint32_t ah[4][4], al[4][4];
            #pragma unroll
            for (int t = 0; t < 4; t++) {
                const uint32_t offA = (uint32_t)((m_off + t*16 + a_row) * RS + s*8 + a_k) * 4u;
                ldm4(ah[t], sbase + offA);
                ldm4(al[t], sbase + PLANE*4u + offA);
            }
            uint32_t bh[2][4], bl[2][4];
            #pragma unroll
            for (int u2 = 0; u2 < 2; u2++) {
                const uint32_t offB = (uint32_t)((n_off + u2*16 + b_row) * RS + s*8 + b_k) * 4u;
                ldm4(bh[u2], sbase + 2u*PLANE*4u + offB);
                ldm4(bl[u2], sbase + 3u*PLANE*4u + offB);
            }
            #pragma unroll
            for (int u2 = 0; u2 < 2; u2++)
                #pragma unroll
                for (int p = 0; p < 2; p++) {
                    const int u = u2 * 2 + p;
                    #pragma unroll
                    for (int t = 0; t < 4; t++) {
                        mma16(acc[t][u], ah[t], bh[u2][2*p], bh[u2][2*p+1]);
                        mma16(acc[t][u], ah[t], bl[u2][2*p], bl[u2][2*p+1]);
                        mma16(acc[t][u], al[t], bh[u2][2*p], bh[u2][2*p+1]);
                    }
                }
        }

        if (c + 1 < NIT) SPLIT_STORE((c + 1) & 1);
        __syncthreads();
    }

    const bool hasb = (bias != nullptr);
    #pragma unroll
    for (int u = 0; u < 4; u++) {
        const int ncol = n0 + n_off + u * 8 + tig * 2;
        float2 bv = make_float2(0.f, 0.f);
        if (hasb) bv = *reinterpret_cast<const float2*>(bias + ncol);
        #pragma unroll
        for (int t = 0; t < 4; t++) {
            const int r = m0 + m_off + t * 16 + grp;
            *reinterpret_cast<float2*>(C + (size_t)r * DD + ncol) =
                make_float2(acc[t][u][0] + bv.x, acc[t][u][1] + bv.y);
            *reinterpret_cast<float2*>(C + (size_t)(r + 8) * DD + ncol) =
                make_float2(acc[t][u][2] + bv.x, acc[t][u][3] + bv.y);
        }
    }
    #undef SPLIT_STORE
}

// ---------------------------------------------------------------------------
// Causal flash attention, fp16 mma + ldmatrix fragments.
// ---------------------------------------------------------------------------
__global__ __launch_bounds__(256, 1)
void attn_mma(const float* __restrict__ gq, const float* __restrict__ gk,
              const float* __restrict__ gv, float* __restrict__ gc)
{
    extern __shared__ float smf[];
    float* Khi  = smf;
    float* Klo  = smf + 64*K36;
    float* Vthi = smf + 2*64*K36;
    float* Vtlo = smf + 3*64*K36;
    float* Ps   = smf + PSOFF;
    const uint32_t smb   = smem_u32(smf);
    const uint32_t aKhi  = smb;
    const uint32_t aKlo  = smb + 64u*K36*4u;
    const uint32_t aVthi = smb + 2u*64u*K36*4u;
    const uint32_t aVtlo = smb + 3u*64u*K36*4u;
    const uint32_t aPs   = smb + (uint32_t)PSOFF*4u;

    const int tid  = threadIdx.x;
    const int w    = tid >> 5, lane = tid & 31;
    const int grp  = lane >> 2, tig = lane & 3;
    const int wrow = w * 16;
    const int h    = blockIdx.y, b = blockIdx.z;
    const int st   = gridDim.x - 1 - blockIdx.x;
    const int s0   = st * TQ;

    const int a_row = lane & 15;
    const int a_k   = (lane >> 4) * 4;
    const int b_row = (lane & 7) + ((lane >> 1) & 8);
    const int b_k   = ((lane >> 3) & 1) * 4;

    const float* qb = gq + ((size_t)b * SS + s0) * DD + h * DKK;
    const float* kb = gk + (size_t)b * SS * DD + h * DKK;
    const float* vb = gv + (size_t)b * SS * DD + h * DKK;

    // ---- stage Q split (Qhi->Ps, Qlo->Khi area) ----
    {
        float* Qlo = smf;
        #pragma unroll
        for (int u = 0; u < 4; u++) {
            int f = tid + u * 256;
            int row = f >> 3, oct = f & 7;
            float4 x0 = *reinterpret_cast<const float4*>(qb + (size_t)row * DD + oct * 8);
            float4 x1 = *reinterpret_cast<const float4*>(qb + (size_t)row * DD + oct * 8 + 4);
            uint4 hi, lo;
            split8(x0, x1, hi, lo);
            *reinterpret_cast<uint4*>(Ps  + row * K36 + oct * 4) = hi;
            *reinterpret_cast<uint4*>(Qlo + row * K36 + oct * 4) = lo;
        }
    }
    __syncthreads();
    uint32_t aqh[4][4], aql[4][4];
    #pragma unroll
    for (int ks = 0; ks < 4; ks++) {
        const uint32_t offQ = (uint32_t)((wrow + a_row) * K36 + ks*8 + a_k) * 4u;
        ldm4(aqh[ks], aPs + offQ);
        ldm4(aql[ks], smb + offQ);
    }
    __syncthreads();

    // prefetch K/V tile 0
    const int kr0 = tid >> 3, ko0 = tid & 7;
    const int kr1 = (tid + 256) >> 3;
    const int vl  = lane, vw8 = w * 8;
    float4 kreg[2][2], vreg[4];
    #pragma unroll
    for (int u = 0; u < 2; u++) {
        const int rr = u ? kr1 : kr0;
        kreg[u][0] = *reinterpret_cast<const float4*>(kb + (size_t)rr * DD + ko0 * 8);
        kreg[u][1] = *reinterpret_cast<const float4*>(kb + (size_t)rr * DD + ko0 * 8 + 4);
    }
    vreg[0] = *reinterpret_cast<const float4*>(vb + (size_t)(2*vl)   * DD + vw8);
    vreg[1] = *reinterpret_cast<const float4*>(vb + (size_t)(2*vl)   * DD + vw8 + 4);
    vreg[2] = *reinterpret_cast<const float4*>(vb + (size_t)(2*vl+1) * DD + vw8);
    vreg[3] = *reinterpret_cast<const float4*>(vb + (size_t)(2*vl+1) * DD + vw8 + 4);

    float m0r = -1e30f, m1r = -1e30f, l0 = 0.f, l1 = 0.f;
    float of[8][4];
    #pragma unroll
    for (int nt = 0; nt < 8; nt++)
        #pragma unroll
        for (int q = 0; q < 4; q++) of[nt][q] = 0.f;

    const int ntiles = s0 / TKV + 2;
    for (int tt = 0; tt < ntiles; ++tt) {
        #pragma unroll
        for (int u = 0; u < 2; u++) {
            const int rr = u ? kr1 : kr0;
            uint4 hi, lo;
            split8(kreg[u][0], kreg[u][1], hi, lo);
            *reinterpret_cast<uint4*>(Khi + rr * K36 + ko0 * 4) = hi;
            *reinterpret_cast<uint4*>(Klo + rr * K36 + ko0 * 4) = lo;
        }
        {
            const float* a0 = reinterpret_cast<const float*>(&vreg[0]);
            const float* a1 = reinterpret_cast<const float*>(&vreg[2]);
            #pragma unroll
            for (int j = 0; j < 8; j++) {
                float x = a0[j], y = a1[j];
                __half2 hh = __floats2half2_rn(x, y);
                float2 hf = __half22float2(hh);
                __half2 ll = __floats2half2_rn(x - hf.x, y - hf.y);
                Vthi[(vw8 + j) * K36 + vl] = __uint_as_float(*(uint32_t*)&hh);
                Vtlo[(vw8 + j) * K36 + vl] = __uint_as_float(*(uint32_t*)&ll);
            }
        }
        __syncthreads();

        if (tt + 1 < ntiles) {
            const int t0n = (tt + 1) * TKV;
            #pragma unroll
            for (int u = 0; u < 2; u++) {
                const int rr = (u ? kr1 : kr0) + t0n;
                kreg[u][0] = *reinterpret_cast<const float4*>(kb + (size_t)rr * DD + ko0 * 8);
                kreg[u][1] = *reinterpret_cast<const float4*>(kb + (size_t)rr * DD + ko0 * 8 + 4);
            }
            vreg[0] = *reinterpret_cast<const float4*>(vb + (size_t)(t0n+2*vl)   * DD + vw8);
            vreg[1] = *reinterpret_cast<const float4*>(vb + (size_t)(t0n+2*vl)   * DD + vw8 + 4);
            vreg[2] = *reinterpret_cast<const float4*>(vb + (size_t)(t0n+2*vl+1) * DD + vw8);
            vreg[3] = *reinterpret_cast<const float4*>(vb + (size_t)(t0n+2*vl+1) * DD + vw8 + 4);
        }

        // ---- S = Q K^T (fp16 x3) ----
        float sf[8][4];
        #pragma unroll
        for (int nt = 0; nt < 8; nt++)
            #pragma unroll
            for (int q = 0; q < 4; q++) sf[nt][q] = 0.f;

        #pragma unroll
        for (int ks = 0; ks < 4; ks++) {
            #pragma unroll
            for (int nt2 = 0; nt2 < 4; nt2++) {
                const uint32_t offK = (uint32_t)((nt2*16 + b_row) * K36 + ks*8 + b_k) * 4u;
                uint32_t rh[4], rl[4];
                ldm4(rh, aKhi + offK);
                ldm4(rl, aKlo + offK);
                mma16(sf[2*nt2],   aqh[ks], rh[0], rh[1]);
                mma16(sf[2*nt2],   aql[ks], rh[0], rh[1]);
                mma16(sf[2*nt2],   aqh[ks], rl[0], rl[1]);
                mma16(sf[2*nt2+1], aqh[ks], rh[2], rh[3]);
                mma16(sf[2*nt2+1], aql[ks], rh[2], rh[3]);
                mma16(sf[2*nt2+1], aqh[ks], rl[2], rl[3]);
            }
        }

        const int t0 = tt * TKV;
        #pragma unroll
        for (int nt = 0; nt < 8; nt++)
            #pragma unroll
            for (int q = 0; q < 4; q++) sf[nt][q] *= 8.0f;
        if (t0 + TKV > s0) {
            const int r0g = s0 + wrow + grp, r1g = r0g + 8;
            #pragma unroll
            for (int nt = 0; nt < 8; nt++) {
                const int c0g = t0 + nt*8 + 2*tig;
                if (c0g     > r0g) sf[nt][0] = -1e30f;
                if (c0g + 1 > r0g) sf[nt][1] = -1e30f;
                if (c0g     > r1g) sf[nt][2] = -1e30f;
                if (c0g + 1 > r1g) sf[nt][3] = -1e30f;
            }
        }

        float mt0 = -1e30f, mt1 = -1e30f;
        #pragma unroll
        for (int nt = 0; nt < 8; nt++) {
            mt0 = fmaxf(mt0, fmaxf(sf[nt][0], sf[nt][1]));
            mt1 = fmaxf(mt1, fmaxf(sf[nt][2], sf[nt][3]));
        }
        mt0 = fmaxf(mt0, __shfl_xor_sync(0xffffffffu, mt0, 1));
        mt0 = fmaxf(mt0, __shfl_xor_sync(0xffffffffu, mt0, 2));
        mt1 = fmaxf(mt1, __shfl_xor_sync(0xffffffffu, mt1, 1));
        mt1 = fmaxf(mt1, __shfl_xor_sync(0xffffffffu, mt1, 2));

        const float mn0 = fmaxf(m0r, mt0), mn1 = fmaxf(m1r, mt1);
        const float a0s = __expf(m0r - mn0), a1s = __expf(m1r - mn1);
        m0r = mn0; m1r = mn1;

        float s0sum = 0.f, s1sum = 0.f;
        #pragma unroll
        for (int nt = 0; nt < 8; nt++) {
            float p0 = __expf(sf[nt][0] - mn0);
            float p1 = __expf(sf[nt][1] - mn0);
            float p2 = __expf(sf[nt][2] - mn1);
            float p3 = __expf(sf[nt][3] - mn1);
            s0sum += p0 + p1; s1sum += p2 + p3;
            __half2 hp0 = __floats2half2_rn(p0, p1);
            __half2 hp1 = __floats2half2_rn(p2, p3);
            Ps[(wrow + grp)     * K36 + nt*4 + tig] = __uint_as_float(*(uint32_t*)&hp0);
            Ps[(wrow + grp + 8) * K36 + nt*4 + tig] = __uint_as_float(*(uint32_t*)&hp1);
        }
        s0sum += __shfl_xor_sync(0xffffffffu, s0sum, 1);
        s0sum += __shfl_xor_sync(0xffffffffu, s0sum, 2);
        s1sum += __shfl_xor_sync(0xffffffffu, s1sum, 1);
        s1sum += __shfl_xor_sync(0xffffffffu, s1sum, 2);
        l0 = l0 * a0s + s0sum;
        l1 = l1 * a1s + s1sum;
        #pragma unroll
        for (int nt = 0; nt < 8; nt++) {
            of[nt][0] *= a0s; of[nt][1] *= a0s;
            of[nt][2] *= a1s; of[nt][3] *= a1s;
        }
        __syncwarp();   // make Ps stores visible to cross-lane ldmatrix reads

        // ---- O += P V (P fp16, V hi/lo) ----  (Ps rows warp-private)
        #pragma unroll
        for (int ks = 0; ks < 4; ks++) {
            uint32_t ap[4];
            const uint32_t offP = (uint32_t)((wrow + a_row) * K36 + ks*8 + a_k) * 4u;
            ldm4(ap, aPs + offP);
            #pragma unroll
            for (int nt2 = 0; nt2 < 4; nt2++) {
                const uint32_t offV = (uint32_t)((nt2*16 + b_row) * K36 + ks*8 + b_k) * 4u;
                uint32_t rh[4], rl[4];
                ldm4(rh, aVthi + offV);
                ldm4(rl, aVtlo + offV);
                mma16(of[2*nt2],   ap, rh[0], rh[1]);
                mma16(of[2*nt2],   ap, rl[0], rl[1]);
                mma16(of[2*nt2+1], ap, rh[2], rh[3]);
                mma16(of[2*nt2+1], ap, rl[2], rl[3]);
            }
        }
        __syncthreads();
    }

    const float inv0 = 1.0f / l0, inv1 = 1.0f / l1;
    float* ob = gc + ((size_t)b * SS + s0 + wrow + grp) * DD + h * DKK;
    #pragma unroll
    for (int nt = 0; nt < 8; nt++) {
        const int col = nt*8 + 2*tig;
        *reinterpret_cast<float2*>(ob + col) =
            make_float2(of[nt][0] * inv0, of[nt][1] * inv0);
        *reinterpret_cast<float2*>(ob + (size_t)8 * DD + col) =
            make_float2(of[nt][2] * inv1, of[nt][3] * inv1);
    }
}

// ---------------------------------------------------------------------------
extern "C" void kernel_launch(void* const* d_in, const int* in_sizes, int n_in,
                              void* d_out, int out_size)
{
    const float* Q  = (const float*)d_in[0];
    const float* K  = (const float*)d_in[1];
    const float* V  = (const float*)d_in[2];
    // d_in[3] = causal mask (unused)
    const float* Wq = (const float*)d_in[4];
    const float* Wk = (const float*)d_in[5];
    const float* Wv = (const float*)d_in[6];
    const float* Wo = (const float*)d_in[7];
    const float* bo = (const float*)d_in[8];
    float* out = (float*)d_out;

    float *gwt, *gq, *gk, *gv, *gc;
    cudaGetSymbolAddress((void**)&gwt, g_wt);
    cudaGetSymbolAddress((void**)&gq,  g_q);
    cudaGetSymbolAddress((void**)&gk,  g_k);
    cudaGetSymbolAddress((void**)&gv,  g_v);
    cudaGetSymbolAddress((void**)&gc,  g_c);
    const size_t WSZ = (size_t)DD * DD;

    cudaFuncSetAttribute(gemm_fp16, cudaFuncAttributeMaxDynamicSharedMemorySize, GEMM_SMEM);
    cudaFuncSetAttribute(attn_mma, cudaFuncAttributeMaxDynamicSharedMemorySize, ATTN_SMEM);

    const dim3 tg(DKK / 32, DD / 32, HH);     // (2, 32, 16)

    transpose_w<<<tg, 256>>>(Wq, gwt);
    transpose_w<<<tg, 256>>>(Wk, gwt + WSZ);
    transpose_w<<<tg, 256>>>(Wv, gwt + 2 * WSZ);

    // fused Q/K/V projections: one launch, 24x64 CTAs
    gemm_fp16<<<dim3(3 * DD / BN, NN / BM), 256, GEMM_SMEM>>>(
        Q, K, V, gwt, nullptr, gq, gk, gv);

    attn_mma<<<dim3(SS/TQ, HH, BB), 256, ATTN_SMEM>>>(gq, gk, gv, gc);

    // output projection (seg always 0)
    gemm_fp16<<<dim3(DD / BN, NN / BM), 256, GEMM_SMEM>>>(
        gc, gc, gc, Wo, bo, out, out, out);
}